// round 1
// baseline (speedup 1.0000x reference)
#include <cuda_runtime.h>
#include <cstdint>

#define NPIX   65536
#define CIMG   256
#define KMASK  9
#define MS     32
#define PITCH  260
#define PROWS  258
#define PPLANE (PROWS*PITCH)   // 67080

// ---------------- scratch (device globals; no allocations allowed) ----------------
__device__ float g_fsm_pad[256*PPLANE];   // padded fsm      (~68.7 MB)
__device__ float g_f1_pad [128*PPLANE];   // padded feat1
__device__ float g_f2_pad [ 64*PPLANE];   // padded feat2
__device__ float g_f3     [ 32*NPIX];     // feat3 (flat)
__device__ float g_wt1    [256*9*128];    // repacked weights [ci][k][co]
__device__ float g_wt2    [128*9*64];
__device__ float g_wt3    [ 64*9*32];
__device__ int   g_bits   [NPIX];         // 9-bit mask membership per pixel
__device__ float g_Spart  [8][KMASK][CIMG];
__device__ int   g_counts [KMASK];
__device__ float g_mean   [KMASK*CIMG];
__device__ unsigned g_validbits;
__device__ float g_covpart[KMASK*16*MS*MS];
__device__ float g_cov    [KMASK*MS*MS];

// ---------------- packed fp32x2 helpers (sm_103a FFMA2) ----------------
__device__ __forceinline__ unsigned long long pk2(float lo, float hi){
    unsigned long long r;
    asm("mov.b64 %0, {%1, %2};" : "=l"(r) : "f"(lo), "f"(hi));
    return r;
}
__device__ __forceinline__ void ffma2(unsigned long long &d, unsigned long long a, unsigned long long b){
    asm("fma.rn.f32x2 %0, %1, %2, %0;" : "+l"(d) : "l"(a), "l"(b));
}

// ---------------- small kernels ----------------
__global__ void k_init(){
    int t = threadIdx.x;
    if (t < KMASK) g_counts[t] = 0;
}

__global__ void k_maskbits(const int* __restrict__ masks){
    int n = blockIdx.x*256 + threadIdx.x;
    int bits = 0;
    #pragma unroll
    for (int k = 0; k < KMASK; k++){
        int on = (masks[k*NPIX + n] > 0) ? 1 : 0;
        bits |= on << k;
        int c = __syncthreads_count(on);
        if (threadIdx.x == 0) atomicAdd(&g_counts[k], c);   // int atomics: deterministic
    }
    g_bits[n] = bits;
}

__global__ void k_sums(const float* __restrict__ x){
    const int c = blockIdx.x, s = blockIdx.y, t = threadIdx.x;
    float ls[KMASK];
    #pragma unroll
    for (int k = 0; k < KMASK; k++) ls[k] = 0.f;
    const float* xc = x + c*NPIX + s*8192;
    const int*   bp = g_bits + s*8192;
    for (int i = 0; i < 32; i++){
        float v = xc[i*256 + t];
        int   b = bp[i*256 + t];
        #pragma unroll
        for (int k = 0; k < KMASK; k++)
            if ((b >> k) & 1) ls[k] += v;
    }
    __shared__ float red[256];
    #pragma unroll
    for (int k = 0; k < KMASK; k++){
        red[t] = ls[k];
        __syncthreads();
        for (int off = 128; off > 0; off >>= 1){
            if (t < off) red[t] += red[t+off];
            __syncthreads();
        }
        if (t == 0) g_Spart[s][k][c] = red[0];
        __syncthreads();
    }
}

__global__ void k_meanvalid(){
    int t = threadIdx.x;   // == channel c, blockDim 256
    for (int k = 0; k < KMASK; k++){
        float s = 0.f;
        #pragma unroll
        for (int p = 0; p < 8; p++) s += g_Spart[p][k][t];
        g_mean[k*CIMG + t] = s / fmaxf((float)g_counts[k], 1.f);
    }
    if (t == 0){
        unsigned vb = 0;
        for (int k = 0; k < KMASK; k++)
            if (g_counts[k] >= 10) vb |= 1u << k;
        g_validbits = vb;
    }
}

__global__ void k_zeroborders(){
    int b = blockIdx.x, t = threadIdx.x;
    float* base;
    if      (b < 256) base = g_fsm_pad + b*PPLANE;
    else if (b < 384) base = g_f1_pad  + (b-256)*PPLANE;
    else              base = g_f2_pad  + (b-384)*PPLANE;
    if (t < 260){ base[t] = 0.f; base[257*PITCH + t] = 0.f; }
    int row = t + 1;   // rows 1..256
    base[row*PITCH + 0]   = 0.f;
    base[row*PITCH + 257] = 0.f;
    base[row*PITCH + 258] = 0.f;
    base[row*PITCH + 259] = 0.f;
}

__global__ void k_repack(const float* __restrict__ w, float* __restrict__ wt, int Cin, int Cout){
    int id = blockIdx.x*256 + threadIdx.x;
    if (id >= Cin*9*Cout) return;
    int co   = id % Cout;
    int rest = id / Cout;           // ci*9 + k
    wt[id] = w[co*(Cin*9) + rest];
}

__global__ void k_fsm(const float* __restrict__ x, float* __restrict__ out_fsm){
    int t = threadIdx.x;
    #pragma unroll 1
    for (int r = 0; r < 8; r++){
        int flat = blockIdx.x*2048 + r*256 + t;   // c*65536 + n
        int c = flat >> 16;
        int n = flat & 65535;
        unsigned ob = ((unsigned)g_bits[n]) & g_validbits;
        float m = 0.f;
        if (ob) m = g_mean[(31 - __clz(ob))*CIMG + c];
        float v = x[flat] - m;
        out_fsm[flat] = v;
        int y = n >> 8, xx = n & 255;
        g_fsm_pad[c*PPLANE + (y+1)*PITCH + (xx+1)] = v;
    }
}

// ---------------- 3x3 conv as implicit GEMM, fp32x2 packed FMA ----------------
// in:  padded [Cin][258][260], wt: [Cin][9][Cout], out: padded or flat.
// block: 256 thr, tile 64(Cout) x 128(px of one image row); BK = 9 (one ci per step).
template<int BM, int MM, bool RELU, bool PADOUT>
__global__ void __launch_bounds__(256) k_conv3x3(
    const float* __restrict__ inp, const float* __restrict__ wt,
    const float* __restrict__ bias, float* __restrict__ outp,
    int Cin, int Cout)
{
    const int t  = threadIdx.x;
    const int tx = t & 15;          // 8 px each
    const int ty = t >> 4;          // MM couts each
    const int y  = blockIdx.x >> 1;
    const int x0 = (blockIdx.x & 1) << 7;
    const int co0 = blockIdx.y * BM;

    __shared__ float As[9][BM];       // As[k][m] = wt[ci][k][co0+m]
    __shared__ float patch[3][132];   // input rows y..y+2, cols x0..x0+131 (padded coords)

    unsigned long long acc[MM/2][8];
    #pragma unroll
    for (int i = 0; i < MM/2; i++)
        #pragma unroll
        for (int j = 0; j < 8; j++) acc[i][j] = 0ull;

    const float* pin = inp + y*PITCH + x0;
    const float* pw  = wt + co0;
    const int NF4A = 9*BM/4;

    #pragma unroll 1
    for (int ci = 0; ci < Cin; ci++){
        __syncthreads();
        if (t < NF4A){
            int k = t / (BM/4), m4 = t % (BM/4);
            *(float4*)&As[k][m4*4] = *(const float4*)&pw[(ci*9 + k)*Cout + m4*4];
        }
        if (t < 99){
            int r = t / 33, c4 = t % 33;
            *(float4*)&patch[r][c4*4] = *(const float4*)&pin[ci*PPLANE + r*PITCH + c4*4];
        }
        __syncthreads();
        #pragma unroll
        for (int dy = 0; dy < 3; dy++){
            float4 p0 = *(const float4*)&patch[dy][tx*8];
            float4 p1 = *(const float4*)&patch[dy][tx*8 + 4];
            float2 p2 = *(const float2*)&patch[dy][tx*8 + 8];
            float rr[10] = {p0.x,p0.y,p0.z,p0.w,p1.x,p1.y,p1.z,p1.w,p2.x,p2.y};
            unsigned long long bb[10];
            #pragma unroll
            for (int v = 0; v < 10; v++) bb[v] = pk2(rr[v], rr[v]);
            #pragma unroll
            for (int dx = 0; dx < 3; dx++){
                const int k = dy*3 + dx;
                unsigned long long a2[MM/2];
                #pragma unroll
                for (int i = 0; i < MM/2; i++)
                    a2[i] = *(const unsigned long long*)&As[k][ty*MM + i*2];
                #pragma unroll
                for (int j = 0; j < 8; j++)
                    #pragma unroll
                    for (int i = 0; i < MM/2; i++)
                        ffma2(acc[i][j], a2[i], bb[dx+j]);
            }
        }
    }

    #pragma unroll
    for (int i = 0; i < MM/2; i++){
        int coA = co0 + ty*MM + 2*i;
        float bA = bias[coA], bB = bias[coA+1];
        #pragma unroll
        for (int j = 0; j < 8; j++){
            float fx, fy;
            asm("mov.b64 {%0, %1}, %2;" : "=f"(fx), "=f"(fy) : "l"(acc[i][j]));
            float vA = fx + bA, vB = fy + bB;
            if (RELU){ vA = fmaxf(vA, 0.f); vB = fmaxf(vB, 0.f); }
            int xg = x0 + tx*8 + j;
            if (PADOUT){
                outp[ coA   *PPLANE + (y+1)*PITCH + (xg+1)] = vA;
                outp[(coA+1)*PPLANE + (y+1)*PITCH + (xg+1)] = vB;
            } else {
                outp[ coA   *NPIX + y*256 + xg] = vA;
                outp[(coA+1)*NPIX + y*256 + xg] = vB;
            }
        }
    }
}

// ---------------- masked 32x32 covariance (deterministic partials) ----------------
__global__ void __launch_bounds__(256) k_cov(const float* __restrict__ f3){
    const int k = blockIdx.y;
    const int chunk = blockIdx.x;        // 16 chunks of 4096 px
    const int n0 = chunk*4096;
    const int t = threadIdx.x;
    __shared__ float ftile[32*257];      // [c][p], stride 257 (odd -> conflict-free)
    const int pt = t & 63, pg = t >> 6;
    const int ci0 = (pt & 7)*4, di0 = (pt >> 3)*4;

    float acc[4][4];
    #pragma unroll
    for (int a = 0; a < 4; a++)
        #pragma unroll
        for (int b = 0; b < 4; b++) acc[a][b] = 0.f;

    #pragma unroll 1
    for (int st = 0; st < 16; st++){
        int nb = n0 + st*256;
        __syncthreads();
        float mk = ((g_bits[nb + t] >> k) & 1) ? 1.f : 0.f;
        #pragma unroll
        for (int c = 0; c < 32; c++)
            ftile[c*257 + t] = f3[c*NPIX + nb + t] * mk;
        __syncthreads();
        for (int p = pg; p < 256; p += 4){
            float fc[4], fd[4];
            #pragma unroll
            for (int q = 0; q < 4; q++){
                fc[q] = ftile[(ci0+q)*257 + p];
                fd[q] = ftile[(di0+q)*257 + p];
            }
            #pragma unroll
            for (int a = 0; a < 4; a++)
                #pragma unroll
                for (int b = 0; b < 4; b++)
                    acc[a][b] += fd[a]*fc[b];
        }
    }
    __syncthreads();
    float* red = ftile;                  // reuse smem
    #pragma unroll
    for (int a = 0; a < 4; a++)
        #pragma unroll
        for (int b = 0; b < 4; b++)
            red[(pg*64 + pt)*16 + a*4 + b] = acc[a][b];
    __syncthreads();
    if (pg == 0){
        #pragma unroll
        for (int e = 0; e < 16; e++){
            float s = red[pt*16+e] + red[(64+pt)*16+e] + red[(128+pt)*16+e] + red[(192+pt)*16+e];
            int a = e >> 2, b = e & 3;
            g_covpart[(k*16 + chunk)*1024 + (di0+a)*32 + (ci0+b)] = s;
        }
    }
}

__global__ void k_covreduce(){
    int e = blockIdx.x*256 + threadIdx.x;    // 9216
    int k = e >> 10;
    float s = 0.f;
    #pragma unroll
    for (int ch = 0; ch < 16; ch++) s += g_covpart[(k*16 + ch)*1024 + (e & 1023)];
    g_cov[e] = s / fmaxf((float)g_counts[k], 1.f);
}

__global__ void k_trans(const float* __restrict__ fcw, const float* __restrict__ fcb,
                        float* __restrict__ out){
    int gid = blockIdx.x*256 + threadIdx.x;  // 9216
    int k = gid >> 10, j = gid & 1023;
    float s = fcb[j];
    const float* cv = g_cov + k*1024;
    const float* wr = fcw + j*1024;
    #pragma unroll 8
    for (int i = 0; i < 1024; i++) s += cv[i]*wr[i];
    if (g_counts[k] < 10) s = 0.f;
    out[gid] = s;
}

// ---------------- launcher ----------------
extern "C" void kernel_launch(void* const* d_in, const int* in_sizes, int n_in,
                              void* d_out, int out_size)
{
    const float* x     = (const float*)d_in[0];
    const int*   masks = (const int*)  d_in[1];
    const float* w1    = (const float*)d_in[2];
    const float* b1    = (const float*)d_in[3];
    const float* w2    = (const float*)d_in[4];
    const float* b2    = (const float*)d_in[5];
    const float* w3    = (const float*)d_in[6];
    const float* b3    = (const float*)d_in[7];
    const float* fcw   = (const float*)d_in[8];
    const float* fcb   = (const float*)d_in[9];

    float* out       = (float*)d_out;
    float* out_trans = out;                       // [9][1024]
    float* out_fsm   = out + KMASK*MS*MS;         // [256][65536]

    void *p;
    cudaGetSymbolAddress(&p, g_fsm_pad); float* fsm_pad = (float*)p;
    cudaGetSymbolAddress(&p, g_f1_pad);  float* f1      = (float*)p;
    cudaGetSymbolAddress(&p, g_f2_pad);  float* f2      = (float*)p;
    cudaGetSymbolAddress(&p, g_f3);      float* f3      = (float*)p;
    cudaGetSymbolAddress(&p, g_wt1);     float* wt1     = (float*)p;
    cudaGetSymbolAddress(&p, g_wt2);     float* wt2     = (float*)p;
    cudaGetSymbolAddress(&p, g_wt3);     float* wt3     = (float*)p;

    k_init<<<1, 32>>>();
    k_maskbits<<<256, 256>>>(masks);
    k_sums<<<dim3(256, 8), 256>>>(x);
    k_meanvalid<<<1, 256>>>();
    k_zeroborders<<<448, 256>>>();
    k_repack<<<(256*9*128 + 255)/256, 256>>>(w1, wt1, 256, 128);
    k_repack<<<(128*9*64  + 255)/256, 256>>>(w2, wt2, 128, 64);
    k_repack<<<( 64*9*32  + 255)/256, 256>>>(w3, wt3, 64, 32);
    k_fsm<<<8192, 256>>>(x, out_fsm);

    k_conv3x3<64, 4, true,  true ><<<dim3(512, 2), 256>>>(fsm_pad, wt1, b1, f1, 256, 128);
    k_conv3x3<64, 4, true,  true ><<<dim3(512, 1), 256>>>(f1,      wt2, b2, f2, 128,  64);
    k_conv3x3<32, 2, false, false><<<dim3(512, 1), 256>>>(f2,      wt3, b3, f3,  64,  32);

    k_cov<<<dim3(16, 9), 256>>>(f3);
    k_covreduce<<<36, 256>>>();
    k_trans<<<36, 256>>>(fcw, fcb, out_trans);
}